// round 1
// baseline (speedup 1.0000x reference)
#include <cuda_runtime.h>
#include <cuda_bf16.h>
#include <math.h>

// Problem constants
// BS=2, N_CAM=6, N_REF=4, N_HEADS=8, EMBD=256, HS=32, L=100, OUT dims (2,100,256)
#define BS     2
#define NCAM   6
#define NREF   4
#define NH     8
#define EMBD   256
#define HS     32
#define L      100
#define KIN    (NCAM*EMBD)      // 1536
#define NKEY   (NCAM*L)         // 600
#define TQ     20               // queries per attention block
#define NQB    (L/TQ)           // 5

// Scratch (static device allocations are allowed)
__device__ float g_Wbar[KIN*EMBD];     // 1536*256 floats
__device__ float g_vbar[BS*L*EMBD];    // 2*100*256

// ---------------------------------------------------------------------------
// K1: Wbar[i,e] = mean over 4 ref-blocks of W_v[i, ref*256+e]; init vbar=bbar
// ---------------------------------------------------------------------------
__global__ void prep_kernel(const float* __restrict__ Wv, const float* __restrict__ bv) {
    int idx = blockIdx.x * 256 + threadIdx.x;          // grid=1536 -> idx < 393216
    int i = idx >> 8, e = idx & 255;
    const float* row = Wv + (size_t)i * (NREF*EMBD);
    g_Wbar[idx] = 0.25f * (row[e] + row[256 + e] + row[512 + e] + row[768 + e]);
    if (idx < BS*L*EMBD) {
        int e2 = idx & 255;
        g_vbar[idx] = 0.25f * (bv[e2] + bv[256 + e2] + bv[512 + e2] + bv[768 + e2]);
    }
}

// ---------------------------------------------------------------------------
// K2: vbar[r,e] += featc[r,:] @ Wbar[:,e]     (r = b*100+l, 200x1536x256)
// featc[r, i] with i = cam*256+ep  ->  sff[b*153600 + cam*25600 + l*256 + ep]
// BM=BN=64, split-K = 8 (192 each), 256 thr, 4x4 microtile, atomicAdd epilogue
// ---------------------------------------------------------------------------
__global__ __launch_bounds__(256)
void gemm_vbar_kernel(const float* __restrict__ sff) {
    __shared__ float As[64][17];
    __shared__ float Bs[16][64];

    const int tx = threadIdx.x & 15;
    const int ty = threadIdx.x >> 4;
    const int colBase = blockIdx.x * 64;
    const int rowBase = blockIdx.y * 64;
    const int k0 = blockIdx.z * 192;

    float acc[4][4];
    #pragma unroll
    for (int i = 0; i < 4; ++i)
        #pragma unroll
        for (int j = 0; j < 4; ++j) acc[i][j] = 0.f;

    for (int kt = 0; kt < 192; kt += 16) {
        const int i0 = k0 + kt;
        // A tile 64x16
        #pragma unroll
        for (int j = 0; j < 4; ++j) {
            int idx = threadIdx.x + j * 256;
            int rr = idx >> 4, kk = idx & 15;
            int r = rowBase + rr;
            float v = 0.f;
            if (r < BS*L) {
                int bb = r / L, l = r - bb * L;
                int i = i0 + kk;
                int cam = i >> 8, ep = i & 255;
                v = sff[bb*153600 + cam*25600 + l*256 + ep];
            }
            As[rr][kk] = v;
        }
        // B tile 16x64
        #pragma unroll
        for (int j = 0; j < 4; ++j) {
            int idx = threadIdx.x + j * 256;
            int kk = idx >> 6, cc = idx & 63;
            Bs[kk][cc] = g_Wbar[(i0 + kk) * 256 + colBase + cc];
        }
        __syncthreads();
        #pragma unroll
        for (int kk = 0; kk < 16; ++kk) {
            float a[4], bb[4];
            #pragma unroll
            for (int i = 0; i < 4; ++i) a[i] = As[ty*4 + i][kk];
            #pragma unroll
            for (int j = 0; j < 4; ++j) bb[j] = Bs[kk][tx*4 + j];
            #pragma unroll
            for (int i = 0; i < 4; ++i)
                #pragma unroll
                for (int j = 0; j < 4; ++j) acc[i][j] = fmaf(a[i], bb[j], acc[i][j]);
        }
        __syncthreads();
    }
    #pragma unroll
    for (int i = 0; i < 4; ++i) {
        int r = rowBase + ty*4 + i;
        if (r < BS*L) {
            #pragma unroll
            for (int j = 0; j < 4; ++j)
                atomicAdd(&g_vbar[r*256 + colBase + tx*4 + j], acc[i][j]);
        }
    }
}

// ---------------------------------------------------------------------------
// K3: attention, collapsed. Block = (qtile, head, batch). 80 blocks, 256 thr.
//   s[q,k]  = (Q[q]/sqrt32) . K[k]                     (k = cam*100 + l')
//   w[q,l'] = sum_cam exp(s[q,cam,l'] - m) / Z         (Z over all 600)
//   out[q]  = sum_l' w[q,l'] * vbar[l']
// ---------------------------------------------------------------------------
#define KT_STRIDE 601
#define SMEM_BYTES ((32*KT_STRIDE + L*HS + TQ*HS + TQ*NKEY + TQ*L) * 4)

__global__ __launch_bounds__(256, 1)
void attn_kernel(const float* __restrict__ sff, const float* __restrict__ bq,
                 float* __restrict__ out) {
    extern __shared__ float sm[];
    float* Kt = sm;                       // [32][601] transposed keys
    float* Vs = Kt + 32*KT_STRIDE;        // [100][32]
    float* Qs = Vs + L*HS;                // [20][32] (pre-scaled)
    float* S  = Qs + TQ*HS;               // [20][600]
    float* Ws = S  + TQ*NKEY;             // [20][100]

    const int tid = threadIdx.x;
    const int qb = blockIdx.x, h = blockIdx.y, b = blockIdx.z;

    // ---- loads ----
    for (int idx = tid; idx < NKEY*HS; idx += 256) {
        int k = idx >> 5, d = idx & 31;
        int cam = k / L, lp = k - cam * L;
        Kt[d*KT_STRIDE + k] = sff[(b*NCAM + cam)*25600 + lp*256 + h*32 + d];
    }
    for (int idx = tid; idx < L*HS; idx += 256) {
        int lp = idx >> 5, d = idx & 31;
        Vs[idx] = g_vbar[(b*L + lp)*256 + h*32 + d];
    }
    for (int idx = tid; idx < TQ*HS; idx += 256) {
        int q = idx >> 5, d = idx & 31;
        Qs[idx] = bq[(b*L + qb*TQ + q)*256 + h*32 + d] * 0.17677669529663687f; // 1/sqrt(32)
    }
    __syncthreads();

    // ---- scores: each half (128 thr) does 10 queries x all 600 keys ----
    {
        const int half = tid >> 7;
        const int th = tid & 127;
        const int qbase = half * 10;
        float acc[10][5];
        #pragma unroll
        for (int q = 0; q < 10; ++q)
            #pragma unroll
            for (int j = 0; j < 5; ++j) acc[q][j] = 0.f;

        #pragma unroll 2
        for (int d = 0; d < 32; ++d) {
            float kv[5];
            #pragma unroll
            for (int j = 0; j < 5; ++j) {
                int k = th + 128*j;
                kv[j] = (k < NKEY) ? Kt[d*KT_STRIDE + k] : 0.f;
            }
            #pragma unroll
            for (int q = 0; q < 10; ++q) {
                float qv = Qs[(qbase + q)*32 + d];
                #pragma unroll
                for (int j = 0; j < 5; ++j) acc[q][j] = fmaf(qv, kv[j], acc[q][j]);
            }
        }
        #pragma unroll
        for (int q = 0; q < 10; ++q)
            #pragma unroll
            for (int j = 0; j < 5; ++j) {
                int k = th + 128*j;
                if (k < NKEY) S[(qbase + q)*NKEY + k] = acc[q][j];
            }
    }
    __syncthreads();

    // ---- softmax weights: warp per query (loop) ----
    {
        int w = tid >> 5, lane = tid & 31;
        for (int q = w; q < TQ; q += 8) {
            float m = -1e30f;
            for (int k = lane; k < NKEY; k += 32) m = fmaxf(m, S[q*NKEY + k]);
            #pragma unroll
            for (int off = 16; off; off >>= 1)
                m = fmaxf(m, __shfl_xor_sync(0xffffffffu, m, off));
            float s = 0.f;
            for (int k = lane; k < NKEY; k += 32) s += __expf(S[q*NKEY + k] - m);
            #pragma unroll
            for (int off = 16; off; off >>= 1)
                s += __shfl_xor_sync(0xffffffffu, s, off);
            float inv = 1.0f / s;
            for (int lp = lane; lp < L; lp += 32) {
                float ws = 0.f;
                #pragma unroll
                for (int cam = 0; cam < NCAM; ++cam)
                    ws += __expf(S[q*NKEY + cam*L + lp] - m);
                Ws[q*L + lp] = ws * inv;
            }
        }
    }
    __syncthreads();

    // ---- output: out[q,d] = sum_l' Ws[q,l'] * Vs[l',d] ----
    {
        int d = tid & 31, wq = tid >> 5;
        for (int q = wq; q < TQ; q += 8) {
            float acc = 0.f;
            #pragma unroll 4
            for (int lp = 0; lp < L; ++lp)
                acc = fmaf(Ws[q*L + lp], Vs[lp*32 + d], acc);
            out[(b*L + qb*TQ + q)*256 + h*32 + d] = acc;
        }
    }
}

// ---------------------------------------------------------------------------
extern "C" void kernel_launch(void* const* d_in, const int* in_sizes, int n_in,
                              void* d_out, int out_size) {
    const float* sff = (const float*)d_in[0];   // (2,1,6,256,10,10)
    const float* bq  = (const float*)d_in[1];   // (2,100,256)
    const float* Wv  = (const float*)d_in[2];   // (1536,1024)
    const float* bv  = (const float*)d_in[3];   // (1024,)
    float* out = (float*)d_out;                 // (2,100,256)

    cudaFuncSetAttribute(attn_kernel, cudaFuncAttributeMaxDynamicSharedMemorySize,
                         SMEM_BYTES);

    prep_kernel<<<(KIN*EMBD)/256, 256>>>(Wv, bv);
    gemm_vbar_kernel<<<dim3(4, 4, 8), 256>>>(sff);
    attn_kernel<<<dim3(NQB, NH, BS), 256, SMEM_BYTES>>>(sff, bq, out);
}